// round 13
// baseline (speedup 1.0000x reference)
#include <cuda_runtime.h>
#include <cstdint>

#define EDIM 98304
#define PAD  133
#define NFS  (8 * PAD)   // 1064, nf row stride

// Weights in exact mma A-fragment order: [kind][mat][a][ks][mf][lane][4] (tf32 bits)
__device__ uint32_t g_Wfrag[4 * 3 * 32768];
// Features: [kind][e][ s(0..31) | vx(32..63) | vy(64..95) | vz(96..127) ]
__device__ float g_F[(size_t)4 * EDIM * 128];

#define MMA(c, A, b0, b1) \
    asm volatile("mma.sync.aligned.m16n8k8.row.col.f32.tf32.tf32.f32 " \
        "{%0,%1,%2,%3},{%4,%5,%6,%7},{%8,%9},{%0,%1,%2,%3};" \
        : "+f"((c)[0]), "+f"((c)[1]), "+f"((c)[2]), "+f"((c)[3]) \
        : "r"((A).x), "r"((A).y), "r"((A).z), "r"((A).w), "r"(b0), "r"(b1))

__device__ __forceinline__ uint32_t cvt_tf32(float p) {
    uint32_t u;
    asm("cvt.rn.tf32.f32 %0, %1;" : "=r"(u) : "f"(p));
    return u;
}

// ---------------------------------------------------------------------------
// prep (merged): blocks [0,1536) weights, [1536, 9728) features. 256 thr.
// ---------------------------------------------------------------------------
__global__ void prep(const float* __restrict__ x,
                     const float* __restrict__ Ws, const float* __restrict__ Wf,
                     const float* __restrict__ Wn, const float* __restrict__ Wa) {
    if (blockIdx.x < 1536) {
        int i = blockIdx.x * 256 + threadIdx.x;
        int c    = i & 3;
        int lane = (i >> 2) & 31;
        int mf   = (i >> 7) & 1;
        int ks   = (i >> 8) & 3;
        int a    = (i >> 10) & 31;
        int mk   = i >> 15;
        int mat = mk % 3, kind = mk / 3;
        const float* W = (kind == 0) ? Ws : (kind == 1) ? Wf : (kind == 2) ? Wn : Wa;
        const float norm = 0.022097086912079608f;
        const float i3   = 0.5773502691896258f;
        int g = lane >> 2, tig = lane & 3;
        int w = g + 8 * (c & 1) + 16 * mf;
        int j = 8 * ks + tig + 4 * (c >> 1);
        float val;
        if      (mat == 0) val = norm * W[(a * 32 + j) * 32 + w];
        else if (mat == 1) val = norm * i3 * W[32768 + (a * 32 + j) * 32 + w];
        else               val = norm * (W[65536 + (a * 32 + j) * 32 + w] +
                                         W[98304 + (j * 32 + a) * 32 + w]);
        g_Wfrag[i] = cvt_tf32(val);
    } else {
        int b  = (blockIdx.x - 1536) * 2 + (threadIdx.x >> 7);
        int ch = threadIdx.x & 127;
        const float* xb = x + (size_t)b * 6 * 128 + ch;
        float xv[6];
        #pragma unroll
        for (int q = 0; q < 6; q++) xv[q] = xb[q * 128];
        float r0 = xv[0]+xv[1]+xv[2], r1 = xv[3]+xv[4]+xv[5];
        float c0 = xv[0]+xv[3], c1 = xv[1]+xv[4], c2 = xv[2]+xv[5];
        float tot = r0 + r1;
        int pos = (ch < 32) ? ch : 32 + ((ch - 32) % 3) * 32 + (ch - 32) / 3;
        #pragma unroll
        for (int i = 0; i < 2; i++) {
            float ri = i ? r1 : r0;
            #pragma unroll
            for (int jj = 0; jj < 3; jj++) {
                float cj = (jj == 0) ? c0 : (jj == 1) ? c1 : c2;
                float xs = xv[i * 3 + jj];
                float vals[4] = { xs, (ri - xs) * 0.5f, (cj - xs),
                                  (tot - ri - cj + xs) * 0.5f };
                size_t e = (size_t)b * 6 + i * 3 + jj;
                #pragma unroll
                for (int t = 0; t < 4; t++)
                    g_F[((size_t)t * EDIM + e) * 128 + pos] = vals[t];
            }
        }
    }
}

// ---------------------------------------------------------------------------
__device__ __forceinline__ void stage_tile(float* FS, int kind, int tileBase, int tid) {
    const float* src = g_F + ((size_t)kind * EDIM + tileBase + tid) * 128;
    float* dst = FS + tid * PAD;
    #pragma unroll 8
    for (int q = 0; q < 32; ++q) {
        float4 v = ((const float4*)src)[q];
        dst[q*4+0] = v.x; dst[q*4+1] = v.y; dst[q*4+2] = v.z; dst[q*4+3] = v.w;
    }
}

// ---------------------------------------------------------------------------
// Main: 768 CTAs x 128 threads. Two passes; A-frag LDGs software-pipelined.
// ---------------------------------------------------------------------------
__global__ void __launch_bounds__(128, 2) petp_mma(float* __restrict__ out) {
    extern __shared__ float FS[];   // 128 x 133
    const int tid = threadIdx.x, warp = tid >> 5, lane = tid & 31;
    const int g = lane >> 2, tig = lane & 3;
    const int tileBase = blockIdx.x * 128;
    const int e0 = tileBase + warp * 32;
    const float* fr0 = FS + (warp * 32 + g) * PAD;

    // ================= pass 0: y_s = scalar + gram sections =================
    {
        float acc[2][4][4];
        #pragma unroll
        for (int mf = 0; mf < 2; ++mf)
            #pragma unroll
            for (int nf = 0; nf < 4; ++nf)
                #pragma unroll
                for (int q = 0; q < 4; ++q) acc[mf][nf][q] = 0.f;

        for (int kind = 0; kind < 4; ++kind) {
            __syncthreads();
            stage_tile(FS, kind, tileBase, tid);
            __syncthreads();

            float bs[4][8];
            #pragma unroll
            for (int nf = 0; nf < 4; ++nf)
                #pragma unroll
                for (int jj = 0; jj < 8; ++jj)
                    bs[nf][jj] = fr0[nf * NFS + tig + 4 * jj];

            const uint4* wp0 = (const uint4*)g_Wfrag + (kind * 3 + 0) * 8192;
            const uint4* wp1 = (const uint4*)g_Wfrag + (kind * 3 + 1) * 8192;

            uint4 S0[2][4], S1[2][4], G0[2][4], G1[2][4];
            #pragma unroll
            for (int ks = 0; ks < 4; ++ks) {
                S0[0][ks] = wp0[ks * 64 + lane];
                S1[0][ks] = wp0[ks * 64 + 32 + lane];
                G0[0][ks] = wp1[ks * 64 + lane];
                G1[0][ks] = wp1[ks * 64 + 32 + lane];
            }

            #pragma unroll 2
            for (int a = 0; a < 32; ++a) {
                const int cur = a & 1, nxt = cur ^ 1;
                if (a < 31) {
                    #pragma unroll
                    for (int ks = 0; ks < 4; ++ks) {
                        S0[nxt][ks] = wp0[(a+1) * 256 + ks * 64 + lane];
                        S1[nxt][ks] = wp0[(a+1) * 256 + ks * 64 + 32 + lane];
                        G0[nxt][ks] = wp1[(a+1) * 256 + ks * 64 + lane];
                        G1[nxt][ks] = wp1[(a+1) * 256 + ks * 64 + 32 + lane];
                    }
                }
                float al[4], av[4][3];
                #pragma unroll
                for (int nf = 0; nf < 4; ++nf) {
                    al[nf] = fr0[nf * NFS + a];
                    #pragma unroll
                    for (int k = 0; k < 3; ++k)
                        av[nf][k] = fr0[nf * NFS + 32 + 32 * k + a];
                }
                #pragma unroll
                for (int ks = 0; ks < 4; ++ks) {
                    #pragma unroll
                    for (int nf = 0; nf < 4; ++nf) {
                        uint32_t b0 = cvt_tf32(al[nf] * bs[nf][2 * ks]);
                        uint32_t b1 = cvt_tf32(al[nf] * bs[nf][2 * ks + 1]);
                        MMA(acc[0][nf], S0[cur][ks], b0, b1);
                        MMA(acc[1][nf], S1[cur][ks], b0, b1);
                        int cj = tig + 8 * ks;
                        float p0 = fmaf(av[nf][0], fr0[nf*NFS + 32 + cj],
                                   fmaf(av[nf][1], fr0[nf*NFS + 64 + cj],
                                        av[nf][2] * fr0[nf*NFS + 96 + cj]));
                        float p1 = fmaf(av[nf][0], fr0[nf*NFS + 36 + cj],
                                   fmaf(av[nf][1], fr0[nf*NFS + 68 + cj],
                                        av[nf][2] * fr0[nf*NFS + 100 + cj]));
                        uint32_t q0 = cvt_tf32(p0), q1 = cvt_tf32(p1);
                        MMA(acc[0][nf], G0[cur][ks], q0, q1);
                        MMA(acc[1][nf], G1[cur][ks], q0, q1);
                    }
                }
            }
        }
        #pragma unroll
        for (int mf = 0; mf < 2; ++mf)
            #pragma unroll
            for (int nf = 0; nf < 4; ++nf) {
                int e  = e0 + 8 * nf + 2 * tig;
                int w1 = g + 16 * mf, w2 = w1 + 8;
                float* o = out + (size_t)e * 128;
                o[w1]       = acc[mf][nf][0];
                o[128 + w1] = acc[mf][nf][1];
                o[w2]       = acc[mf][nf][2];
                o[128 + w2] = acc[mf][nf][3];
            }
    }

    // ================= pass V: y_v, 3 components share mat2 frags =================
    {
        float acc[3][2][4][4];
        #pragma unroll
        for (int k = 0; k < 3; ++k)
            #pragma unroll
            for (int mf = 0; mf < 2; ++mf)
                #pragma unroll
                for (int nf = 0; nf < 4; ++nf)
                    #pragma unroll
                    for (int q = 0; q < 4; ++q) acc[k][mf][nf][q] = 0.f;

        for (int kind = 0; kind < 4; ++kind) {
            __syncthreads();
            stage_tile(FS, kind, tileBase, tid);
            __syncthreads();

            const uint4* wp2 = (const uint4*)g_Wfrag + (kind * 3 + 2) * 8192;

            uint4 V0[2][4], V1[2][4];
            #pragma unroll
            for (int ks = 0; ks < 4; ++ks) {
                V0[0][ks] = wp2[ks * 64 + lane];
                V1[0][ks] = wp2[ks * 64 + 32 + lane];
            }

            #pragma unroll 2
            for (int a = 0; a < 32; ++a) {
                const int cur = a & 1, nxt = cur ^ 1;
                if (a < 31) {
                    #pragma unroll
                    for (int ks = 0; ks < 4; ++ks) {
                        V0[nxt][ks] = wp2[(a+1) * 256 + ks * 64 + lane];
                        V1[nxt][ks] = wp2[(a+1) * 256 + ks * 64 + 32 + lane];
                    }
                }
                float al[4];
                #pragma unroll
                for (int nf = 0; nf < 4; ++nf) al[nf] = fr0[nf * NFS + a];

                #pragma unroll
                for (int ks = 0; ks < 4; ++ks) {
                    #pragma unroll
                    for (int nf = 0; nf < 4; ++nf) {
                        int cj = tig + 8 * ks;
                        #pragma unroll
                        for (int k = 0; k < 3; ++k) {
                            uint32_t b0 = cvt_tf32(al[nf] * fr0[nf*NFS + 32 + 32*k + cj]);
                            uint32_t b1 = cvt_tf32(al[nf] * fr0[nf*NFS + 36 + 32*k + cj]);
                            MMA(acc[k][0][nf], V0[cur][ks], b0, b1);
                            MMA(acc[k][1][nf], V1[cur][ks], b0, b1);
                        }
                    }
                }
            }
        }
        #pragma unroll
        for (int k = 0; k < 3; ++k)
            #pragma unroll
            for (int mf = 0; mf < 2; ++mf)
                #pragma unroll
                for (int nf = 0; nf < 4; ++nf) {
                    int e  = e0 + 8 * nf + 2 * tig;
                    int w1 = g + 16 * mf, w2 = w1 + 8;
                    int of1 = 32 + 3 * w1 + k;
                    int of2 = 32 + 3 * w2 + k;
                    float* o = out + (size_t)e * 128;
                    o[of1]       = acc[k][mf][nf][0];
                    o[128 + of1] = acc[k][mf][nf][1];
                    o[of2]       = acc[k][mf][nf][2];
                    o[128 + of2] = acc[k][mf][nf][3];
                }
    }
}

// ---------------------------------------------------------------------------
extern "C" void kernel_launch(void* const* d_in, const int* in_sizes, int n_in,
                              void* d_out, int out_size) {
    const float* x  = (const float*)d_in[0];
    const float* Ws = (const float*)d_in[1];
    const float* Wf = (const float*)d_in[2];
    const float* Wn = (const float*)d_in[3];
    const float* Wa = (const float*)d_in[4];

    const int smem = 128 * PAD * 4;   // 68096 B
    cudaFuncSetAttribute(petp_mma, cudaFuncAttributeMaxDynamicSharedMemorySize, smem);

    prep<<<9728, 256>>>(x, Ws, Wf, Wn, Wa);
    petp_mma<<<768, 128, smem>>>((float*)d_out);
}

// round 14
// speedup vs baseline: 1.0729x; 1.0729x over previous
#include <cuda_runtime.h>
#include <cstdint>

#define EDIM 98304
#define PAD  133
#define NFS  (8 * PAD)    // 1064, pass0 nf row stride
#define PADV 68
#define NFSV (8 * PADV)   // 544, passV nf row stride

// Weights in exact mma A-fragment order: [kind][mat][a][ks][mf][lane][4] (tf32 bits)
__device__ uint32_t g_Wfrag[4 * 3 * 32768];
// Features: [kind][e][ s(0..31) | vx(32..63) | vy(64..95) | vz(96..127) ]
__device__ float g_F[(size_t)4 * EDIM * 128];

#define MMA(c, A, b0, b1) \
    asm volatile("mma.sync.aligned.m16n8k8.row.col.f32.tf32.tf32.f32 " \
        "{%0,%1,%2,%3},{%4,%5,%6,%7},{%8,%9},{%0,%1,%2,%3};" \
        : "+f"((c)[0]), "+f"((c)[1]), "+f"((c)[2]), "+f"((c)[3]) \
        : "r"((A).x), "r"((A).y), "r"((A).z), "r"((A).w), "r"(b0), "r"(b1))

__device__ __forceinline__ uint32_t cvt_tf32(float p) {
    uint32_t u;
    asm("cvt.rn.tf32.f32 %0, %1;" : "=r"(u) : "f"(p));
    return u;
}

// ---------------------------------------------------------------------------
// prep (merged): blocks [0,1536) weights, [1536, 9728) features.
// ---------------------------------------------------------------------------
__global__ void prep(const float* __restrict__ x,
                     const float* __restrict__ Ws, const float* __restrict__ Wf,
                     const float* __restrict__ Wn, const float* __restrict__ Wa) {
    if (blockIdx.x < 1536) {
        int i = blockIdx.x * 256 + threadIdx.x;
        int c    = i & 3;
        int lane = (i >> 2) & 31;
        int mf   = (i >> 7) & 1;
        int ks   = (i >> 8) & 3;
        int a    = (i >> 10) & 31;
        int mk   = i >> 15;
        int mat = mk % 3, kind = mk / 3;
        const float* W = (kind == 0) ? Ws : (kind == 1) ? Wf : (kind == 2) ? Wn : Wa;
        const float norm = 0.022097086912079608f;
        const float i3   = 0.5773502691896258f;
        int g = lane >> 2, tig = lane & 3;
        int w = g + 8 * (c & 1) + 16 * mf;
        int j = 8 * ks + tig + 4 * (c >> 1);
        float val;
        if      (mat == 0) val = norm * W[(a * 32 + j) * 32 + w];
        else if (mat == 1) val = norm * i3 * W[32768 + (a * 32 + j) * 32 + w];
        else               val = norm * (W[65536 + (a * 32 + j) * 32 + w] +
                                         W[98304 + (j * 32 + a) * 32 + w]);
        g_Wfrag[i] = cvt_tf32(val);
    } else {
        int b  = (blockIdx.x - 1536) * 2 + (threadIdx.x >> 7);
        int ch = threadIdx.x & 127;
        const float* xb = x + (size_t)b * 6 * 128 + ch;
        float xv[6];
        #pragma unroll
        for (int q = 0; q < 6; q++) xv[q] = xb[q * 128];
        float r0 = xv[0]+xv[1]+xv[2], r1 = xv[3]+xv[4]+xv[5];
        float c0 = xv[0]+xv[3], c1 = xv[1]+xv[4], c2 = xv[2]+xv[5];
        float tot = r0 + r1;
        int pos = (ch < 32) ? ch : 32 + ((ch - 32) % 3) * 32 + (ch - 32) / 3;
        #pragma unroll
        for (int i = 0; i < 2; i++) {
            float ri = i ? r1 : r0;
            #pragma unroll
            for (int jj = 0; jj < 3; jj++) {
                float cj = (jj == 0) ? c0 : (jj == 1) ? c1 : c2;
                float xs = xv[i * 3 + jj];
                float vals[4] = { xs, (ri - xs) * 0.5f, (cj - xs),
                                  (tot - ri - cj + xs) * 0.5f };
                size_t e = (size_t)b * 6 + i * 3 + jj;
                #pragma unroll
                for (int t = 0; t < 4; t++)
                    g_F[((size_t)t * EDIM + e) * 128 + pos] = vals[t];
            }
        }
    }
}

// ---------------------------------------------------------------------------
// Pass 0 kernel: y_s = scalar + gram sections. 768 CTAs x 128 thr.
// ---------------------------------------------------------------------------
__global__ void __launch_bounds__(128, 3) petp_s(float* __restrict__ out) {
    extern __shared__ float FS[];   // 128 x 133
    const int tid = threadIdx.x, warp = tid >> 5, lane = tid & 31;
    const int g = lane >> 2, tig = lane & 3;
    const int tileBase = blockIdx.x * 128;
    const int e0 = tileBase + warp * 32;
    const float* fr0 = FS + (warp * 32 + g) * PAD;

    float acc[2][4][4];
    #pragma unroll
    for (int mf = 0; mf < 2; ++mf)
        #pragma unroll
        for (int nf = 0; nf < 4; ++nf)
            #pragma unroll
            for (int q = 0; q < 4; ++q) acc[mf][nf][q] = 0.f;

    for (int kind = 0; kind < 4; ++kind) {
        __syncthreads();
        {
            const float* src = g_F + ((size_t)kind * EDIM + tileBase + tid) * 128;
            float* dst = FS + tid * PAD;
            #pragma unroll 8
            for (int q = 0; q < 32; ++q) {
                float4 v = ((const float4*)src)[q];
                dst[q*4+0] = v.x; dst[q*4+1] = v.y; dst[q*4+2] = v.z; dst[q*4+3] = v.w;
            }
        }
        __syncthreads();

        float bs[4][8];
        #pragma unroll
        for (int nf = 0; nf < 4; ++nf)
            #pragma unroll
            for (int jj = 0; jj < 8; ++jj)
                bs[nf][jj] = fr0[nf * NFS + tig + 4 * jj];

        const uint4* wp0 = (const uint4*)g_Wfrag + (kind * 3 + 0) * 8192;
        const uint4* wp1 = (const uint4*)g_Wfrag + (kind * 3 + 1) * 8192;

        #pragma unroll 1
        for (int a = 0; a < 32; ++a) {
            uint4 S0[4], S1[4], G0[4], G1[4];
            #pragma unroll
            for (int ks = 0; ks < 4; ++ks) {
                S0[ks] = wp0[a * 256 + ks * 64 + lane];
                S1[ks] = wp0[a * 256 + ks * 64 + 32 + lane];
                G0[ks] = wp1[a * 256 + ks * 64 + lane];
                G1[ks] = wp1[a * 256 + ks * 64 + 32 + lane];
            }
            float al[4], av[4][3];
            #pragma unroll
            for (int nf = 0; nf < 4; ++nf) {
                al[nf] = fr0[nf * NFS + a];
                #pragma unroll
                for (int k = 0; k < 3; ++k)
                    av[nf][k] = fr0[nf * NFS + 32 + 32 * k + a];
            }
            #pragma unroll
            for (int ks = 0; ks < 4; ++ks) {
                #pragma unroll
                for (int nf = 0; nf < 4; ++nf) {
                    uint32_t b0 = cvt_tf32(al[nf] * bs[nf][2 * ks]);
                    uint32_t b1 = cvt_tf32(al[nf] * bs[nf][2 * ks + 1]);
                    MMA(acc[0][nf], S0[ks], b0, b1);
                    MMA(acc[1][nf], S1[ks], b0, b1);
                    int cj = tig + 8 * ks;
                    float p0 = fmaf(av[nf][0], fr0[nf*NFS + 32 + cj],
                               fmaf(av[nf][1], fr0[nf*NFS + 64 + cj],
                                    av[nf][2] * fr0[nf*NFS + 96 + cj]));
                    float p1 = fmaf(av[nf][0], fr0[nf*NFS + 36 + cj],
                               fmaf(av[nf][1], fr0[nf*NFS + 68 + cj],
                                    av[nf][2] * fr0[nf*NFS + 100 + cj]));
                    uint32_t q0 = cvt_tf32(p0), q1 = cvt_tf32(p1);
                    MMA(acc[0][nf], G0[ks], q0, q1);
                    MMA(acc[1][nf], G1[ks], q0, q1);
                }
            }
        }
    }
    #pragma unroll
    for (int mf = 0; mf < 2; ++mf)
        #pragma unroll
        for (int nf = 0; nf < 4; ++nf) {
            int e  = e0 + 8 * nf + 2 * tig;
            int w1 = g + 16 * mf, w2 = w1 + 8;
            float* o = out + (size_t)e * 128;
            o[w1]       = acc[mf][nf][0];
            o[128 + w1] = acc[mf][nf][1];
            o[w2]       = acc[mf][nf][2];
            o[128 + w2] = acc[mf][nf][3];
        }
}

// ---------------------------------------------------------------------------
// Pass V kernel: y_v, one k-component per CTA. grid (768, 3) x 128 thr.
// smem tile: 128 rows x [ s(32) | v_k(32) ] pad 68.
// ---------------------------------------------------------------------------
__global__ void __launch_bounds__(128, 4) petp_v(float* __restrict__ out) {
    extern __shared__ float FV[];   // 128 x 68
    const int tid = threadIdx.x, warp = tid >> 5, lane = tid & 31;
    const int g = lane >> 2, tig = lane & 3;
    const int k = blockIdx.y;
    const int tileBase = blockIdx.x * 128;
    const int e0 = tileBase + warp * 32;
    const float* fr0 = FV + (warp * 32 + g) * PADV;

    float acc[2][4][4];
    #pragma unroll
    for (int mf = 0; mf < 2; ++mf)
        #pragma unroll
        for (int nf = 0; nf < 4; ++nf)
            #pragma unroll
            for (int q = 0; q < 4; ++q) acc[mf][nf][q] = 0.f;

    for (int kind = 0; kind < 4; ++kind) {
        __syncthreads();
        {
            const float4* src = (const float4*)(g_F + ((size_t)kind * EDIM + tileBase + tid) * 128);
            float4* dst = (float4*)(FV + tid * PADV);
            #pragma unroll
            for (int q = 0; q < 8; ++q) dst[q] = src[q];               // s plane
            #pragma unroll
            for (int q = 0; q < 8; ++q) dst[8 + q] = src[8 + 8*k + q]; // v_k plane
        }
        __syncthreads();

        float bv[4][8];
        #pragma unroll
        for (int nf = 0; nf < 4; ++nf)
            #pragma unroll
            for (int jj = 0; jj < 8; ++jj)
                bv[nf][jj] = fr0[nf * NFSV + 32 + tig + 4 * jj];

        const uint4* wp2 = (const uint4*)g_Wfrag + (kind * 3 + 2) * 8192;

        #pragma unroll 1
        for (int a = 0; a < 32; ++a) {
            uint4 V0[4], V1[4];
            #pragma unroll
            for (int ks = 0; ks < 4; ++ks) {
                V0[ks] = wp2[a * 256 + ks * 64 + lane];
                V1[ks] = wp2[a * 256 + ks * 64 + 32 + lane];
            }
            float al[4];
            #pragma unroll
            for (int nf = 0; nf < 4; ++nf) al[nf] = fr0[nf * NFSV + a];

            #pragma unroll
            for (int ks = 0; ks < 4; ++ks) {
                #pragma unroll
                for (int nf = 0; nf < 4; ++nf) {
                    uint32_t b0 = cvt_tf32(al[nf] * bv[nf][2 * ks]);
                    uint32_t b1 = cvt_tf32(al[nf] * bv[nf][2 * ks + 1]);
                    MMA(acc[0][nf], V0[ks], b0, b1);
                    MMA(acc[1][nf], V1[ks], b0, b1);
                }
            }
        }
    }
    #pragma unroll
    for (int mf = 0; mf < 2; ++mf)
        #pragma unroll
        for (int nf = 0; nf < 4; ++nf) {
            int e  = e0 + 8 * nf + 2 * tig;
            int w1 = g + 16 * mf, w2 = w1 + 8;
            int of1 = 32 + 3 * w1 + k;
            int of2 = 32 + 3 * w2 + k;
            float* o = out + (size_t)e * 128;
            o[of1]       = acc[mf][nf][0];
            o[128 + of1] = acc[mf][nf][1];
            o[of2]       = acc[mf][nf][2];
            o[128 + of2] = acc[mf][nf][3];
        }
}

// ---------------------------------------------------------------------------
extern "C" void kernel_launch(void* const* d_in, const int* in_sizes, int n_in,
                              void* d_out, int out_size) {
    const float* x  = (const float*)d_in[0];
    const float* Ws = (const float*)d_in[1];
    const float* Wf = (const float*)d_in[2];
    const float* Wn = (const float*)d_in[3];
    const float* Wa = (const float*)d_in[4];

    const int smemS = 128 * PAD * 4;    // 68096
    const int smemV = 128 * PADV * 4;   // 34816
    cudaFuncSetAttribute(petp_s, cudaFuncAttributeMaxDynamicSharedMemorySize, smemS);
    cudaFuncSetAttribute(petp_v, cudaFuncAttributeMaxDynamicSharedMemorySize, smemV);

    prep<<<9728, 256>>>(x, Ws, Wf, Wn, Wa);
    petp_s<<<768, 128, smemS>>>((float*)d_out);
    petp_v<<<dim3(768, 3), 128, smemV>>>((float*)d_out);
}

// round 15
// speedup vs baseline: 1.0992x; 1.0245x over previous
#include <cuda_runtime.h>
#include <cstdint>

#define EDIM 98304
#define PAD  133
#define NFS  (8 * PAD)    // 1064, pass0 nf row stride
#define PADV 68
#define NFSV (8 * PADV)   // 544, passV nf row stride

// Weights in exact mma A-fragment order: [kind][mat][a][ks][mf][lane][4] (tf32 bits)
__device__ uint32_t g_Wfrag[4 * 3 * 32768];
// Features: [kind][e][ s(0..31) | vx(32..63) | vy(64..95) | vz(96..127) ]
__device__ float g_F[(size_t)4 * EDIM * 128];

// B operands passed as raw fp32 bits: tf32 mma HW reads only the tf32 bit
// positions (implicit RZ truncation) -- saves 2 cvt per MMA pair.
#define MMA(c, A, b0, b1) \
    asm volatile("mma.sync.aligned.m16n8k8.row.col.f32.tf32.tf32.f32 " \
        "{%0,%1,%2,%3},{%4,%5,%6,%7},{%8,%9},{%0,%1,%2,%3};" \
        : "+f"((c)[0]), "+f"((c)[1]), "+f"((c)[2]), "+f"((c)[3]) \
        : "r"((A).x), "r"((A).y), "r"((A).z), "r"((A).w), "f"(b0), "f"(b1))

__device__ __forceinline__ uint32_t cvt_tf32(float p) {
    uint32_t u;
    asm("cvt.rn.tf32.f32 %0, %1;" : "=r"(u) : "f"(p));
    return u;
}

// ---------------------------------------------------------------------------
// prep (merged): blocks [0,1536) weights, [1536, 9728) features.
// ---------------------------------------------------------------------------
__global__ void prep(const float* __restrict__ x,
                     const float* __restrict__ Ws, const float* __restrict__ Wf,
                     const float* __restrict__ Wn, const float* __restrict__ Wa) {
    if (blockIdx.x < 1536) {
        int i = blockIdx.x * 256 + threadIdx.x;
        int c    = i & 3;
        int lane = (i >> 2) & 31;
        int mf   = (i >> 7) & 1;
        int ks   = (i >> 8) & 3;
        int a    = (i >> 10) & 31;
        int mk   = i >> 15;
        int mat = mk % 3, kind = mk / 3;
        const float* W = (kind == 0) ? Ws : (kind == 1) ? Wf : (kind == 2) ? Wn : Wa;
        const float norm = 0.022097086912079608f;
        const float i3   = 0.5773502691896258f;
        int g = lane >> 2, tig = lane & 3;
        int w = g + 8 * (c & 1) + 16 * mf;
        int j = 8 * ks + tig + 4 * (c >> 1);
        float val;
        if      (mat == 0) val = norm * W[(a * 32 + j) * 32 + w];
        else if (mat == 1) val = norm * i3 * W[32768 + (a * 32 + j) * 32 + w];
        else               val = norm * (W[65536 + (a * 32 + j) * 32 + w] +
                                         W[98304 + (j * 32 + a) * 32 + w]);
        g_Wfrag[i] = cvt_tf32(val);
    } else {
        int b  = (blockIdx.x - 1536) * 2 + (threadIdx.x >> 7);
        int ch = threadIdx.x & 127;
        const float* xb = x + (size_t)b * 6 * 128 + ch;
        float xv[6];
        #pragma unroll
        for (int q = 0; q < 6; q++) xv[q] = xb[q * 128];
        float r0 = xv[0]+xv[1]+xv[2], r1 = xv[3]+xv[4]+xv[5];
        float c0 = xv[0]+xv[3], c1 = xv[1]+xv[4], c2 = xv[2]+xv[5];
        float tot = r0 + r1;
        int pos = (ch < 32) ? ch : 32 + ((ch - 32) % 3) * 32 + (ch - 32) / 3;
        #pragma unroll
        for (int i = 0; i < 2; i++) {
            float ri = i ? r1 : r0;
            #pragma unroll
            for (int jj = 0; jj < 3; jj++) {
                float cj = (jj == 0) ? c0 : (jj == 1) ? c1 : c2;
                float xs = xv[i * 3 + jj];
                float vals[4] = { xs, (ri - xs) * 0.5f, (cj - xs),
                                  (tot - ri - cj + xs) * 0.5f };
                size_t e = (size_t)b * 6 + i * 3 + jj;
                #pragma unroll
                for (int t = 0; t < 4; t++)
                    g_F[((size_t)t * EDIM + e) * 128 + pos] = vals[t];
            }
        }
    }
}

// ---------------------------------------------------------------------------
// Pass 0 kernel: y_s = scalar + gram sections. 768 CTAs x 128 thr.
// ---------------------------------------------------------------------------
__global__ void __launch_bounds__(128, 3) petp_s(float* __restrict__ out) {
    extern __shared__ float FS[];   // 128 x 133
    const int tid = threadIdx.x, warp = tid >> 5, lane = tid & 31;
    const int g = lane >> 2, tig = lane & 3;
    const int tileBase = blockIdx.x * 128;
    const int e0 = tileBase + warp * 32;
    const float* fr0 = FS + (warp * 32 + g) * PAD;

    float acc[2][4][4];
    #pragma unroll
    for (int mf = 0; mf < 2; ++mf)
        #pragma unroll
        for (int nf = 0; nf < 4; ++nf)
            #pragma unroll
            for (int q = 0; q < 4; ++q) acc[mf][nf][q] = 0.f;

    for (int kind = 0; kind < 4; ++kind) {
        __syncthreads();
        {
            const float* src = g_F + ((size_t)kind * EDIM + tileBase + tid) * 128;
            float* dst = FS + tid * PAD;
            #pragma unroll 8
            for (int q = 0; q < 32; ++q) {
                float4 v = ((const float4*)src)[q];
                dst[q*4+0] = v.x; dst[q*4+1] = v.y; dst[q*4+2] = v.z; dst[q*4+3] = v.w;
            }
        }
        __syncthreads();

        float bs[4][8];
        #pragma unroll
        for (int nf = 0; nf < 4; ++nf)
            #pragma unroll
            for (int jj = 0; jj < 8; ++jj)
                bs[nf][jj] = fr0[nf * NFS + tig + 4 * jj];

        const uint4* wp0 = (const uint4*)g_Wfrag + (kind * 3 + 0) * 8192;
        const uint4* wp1 = (const uint4*)g_Wfrag + (kind * 3 + 1) * 8192;

        #pragma unroll 1
        for (int a = 0; a < 32; ++a) {
            uint4 S0[4], S1[4], G0[4], G1[4];
            #pragma unroll
            for (int ks = 0; ks < 4; ++ks) {
                S0[ks] = wp0[a * 256 + ks * 64 + lane];
                S1[ks] = wp0[a * 256 + ks * 64 + 32 + lane];
                G0[ks] = wp1[a * 256 + ks * 64 + lane];
                G1[ks] = wp1[a * 256 + ks * 64 + 32 + lane];
            }
            float al[4], av[4][3];
            #pragma unroll
            for (int nf = 0; nf < 4; ++nf) {
                al[nf] = fr0[nf * NFS + a];
                #pragma unroll
                for (int k = 0; k < 3; ++k)
                    av[nf][k] = fr0[nf * NFS + 32 + 32 * k + a];
            }
            #pragma unroll
            for (int ks = 0; ks < 4; ++ks) {
                #pragma unroll
                for (int nf = 0; nf < 4; ++nf) {
                    float b0 = al[nf] * bs[nf][2 * ks];
                    float b1 = al[nf] * bs[nf][2 * ks + 1];
                    MMA(acc[0][nf], S0[ks], b0, b1);
                    MMA(acc[1][nf], S1[ks], b0, b1);
                    int cj = tig + 8 * ks;
                    float p0 = fmaf(av[nf][0], fr0[nf*NFS + 32 + cj],
                               fmaf(av[nf][1], fr0[nf*NFS + 64 + cj],
                                    av[nf][2] * fr0[nf*NFS + 96 + cj]));
                    float p1 = fmaf(av[nf][0], fr0[nf*NFS + 36 + cj],
                               fmaf(av[nf][1], fr0[nf*NFS + 68 + cj],
                                    av[nf][2] * fr0[nf*NFS + 100 + cj]));
                    MMA(acc[0][nf], G0[ks], p0, p1);
                    MMA(acc[1][nf], G1[ks], p0, p1);
                }
            }
        }
    }
    #pragma unroll
    for (int mf = 0; mf < 2; ++mf)
        #pragma unroll
        for (int nf = 0; nf < 4; ++nf) {
            int e  = e0 + 8 * nf + 2 * tig;
            int w1 = g + 16 * mf, w2 = w1 + 8;
            float* o = out + (size_t)e * 128;
            o[w1]       = acc[mf][nf][0];
            o[128 + w1] = acc[mf][nf][1];
            o[w2]       = acc[mf][nf][2];
            o[128 + w2] = acc[mf][nf][3];
        }
}

// ---------------------------------------------------------------------------
// Pass V kernel: y_v, one k-component per CTA. grid (768, 3) x 128 thr.
// ---------------------------------------------------------------------------
__global__ void __launch_bounds__(128, 4) petp_v(float* __restrict__ out) {
    extern __shared__ float FV[];   // 128 x 68
    const int tid = threadIdx.x, warp = tid >> 5, lane = tid & 31;
    const int g = lane >> 2, tig = lane & 3;
    const int k = blockIdx.y;
    const int tileBase = blockIdx.x * 128;
    const int e0 = tileBase + warp * 32;
    const float* fr0 = FV + (warp * 32 + g) * PADV;

    float acc[2][4][4];
    #pragma unroll
    for (int mf = 0; mf < 2; ++mf)
        #pragma unroll
        for (int nf = 0; nf < 4; ++nf)
            #pragma unroll
            for (int q = 0; q < 4; ++q) acc[mf][nf][q] = 0.f;

    for (int kind = 0; kind < 4; ++kind) {
        __syncthreads();
        {
            const float4* src = (const float4*)(g_F + ((size_t)kind * EDIM + tileBase + tid) * 128);
            float4* dst = (float4*)(FV + tid * PADV);
            #pragma unroll
            for (int q = 0; q < 8; ++q) dst[q] = src[q];               // s plane
            #pragma unroll
            for (int q = 0; q < 8; ++q) dst[8 + q] = src[8 + 8*k + q]; // v_k plane
        }
        __syncthreads();

        float bv[4][8];
        #pragma unroll
        for (int nf = 0; nf < 4; ++nf)
            #pragma unroll
            for (int jj = 0; jj < 8; ++jj)
                bv[nf][jj] = fr0[nf * NFSV + 32 + tig + 4 * jj];

        const uint4* wp2 = (const uint4*)g_Wfrag + (kind * 3 + 2) * 8192;

        #pragma unroll 1
        for (int a = 0; a < 32; ++a) {
            uint4 V0[4], V1[4];
            #pragma unroll
            for (int ks = 0; ks < 4; ++ks) {
                V0[ks] = wp2[a * 256 + ks * 64 + lane];
                V1[ks] = wp2[a * 256 + ks * 64 + 32 + lane];
            }
            float al[4];
            #pragma unroll
            for (int nf = 0; nf < 4; ++nf) al[nf] = fr0[nf * NFSV + a];

            #pragma unroll
            for (int ks = 0; ks < 4; ++ks) {
                #pragma unroll
                for (int nf = 0; nf < 4; ++nf) {
                    float b0 = al[nf] * bv[nf][2 * ks];
                    float b1 = al[nf] * bv[nf][2 * ks + 1];
                    MMA(acc[0][nf], V0[ks], b0, b1);
                    MMA(acc[1][nf], V1[ks], b0, b1);
                }
            }
        }
    }
    #pragma unroll
    for (int mf = 0; mf < 2; ++mf)
        #pragma unroll
        for (int nf = 0; nf < 4; ++nf) {
            int e  = e0 + 8 * nf + 2 * tig;
            int w1 = g + 16 * mf, w2 = w1 + 8;
            int of1 = 32 + 3 * w1 + k;
            int of2 = 32 + 3 * w2 + k;
            float* o = out + (size_t)e * 128;
            o[of1]       = acc[mf][nf][0];
            o[128 + of1] = acc[mf][nf][1];
            o[of2]       = acc[mf][nf][2];
            o[128 + of2] = acc[mf][nf][3];
        }
}

// ---------------------------------------------------------------------------
extern "C" void kernel_launch(void* const* d_in, const int* in_sizes, int n_in,
                              void* d_out, int out_size) {
    const float* x  = (const float*)d_in[0];
    const float* Ws = (const float*)d_in[1];
    const float* Wf = (const float*)d_in[2];
    const float* Wn = (const float*)d_in[3];
    const float* Wa = (const float*)d_in[4];

    const int smemS = 128 * PAD * 4;    // 68096
    const int smemV = 128 * PADV * 4;   // 34816
    cudaFuncSetAttribute(petp_s, cudaFuncAttributeMaxDynamicSharedMemorySize, smemS);
    cudaFuncSetAttribute(petp_v, cudaFuncAttributeMaxDynamicSharedMemorySize, smemV);

    prep<<<9728, 256>>>(x, Ws, Wf, Wn, Wa);
    petp_s<<<768, 128, smemS>>>((float*)d_out);
    petp_v<<<dim3(768, 3), 128, smemV>>>((float*)d_out);
}

// round 17
// speedup vs baseline: 1.1370x; 1.0344x over previous
#include <cuda_runtime.h>
#include <cstdint>

#define EDIM 98304
#define PADS 36            // scalar tile row stride: %8==4 -> conflict-free, 16B aligned
#define NFSS (8 * PADS)
#define PADG 100           // gram tile row stride
#define NFSG (8 * PADG)
#define PADV 68            // vector tile row stride
#define NFSV (8 * PADV)

// Weights in exact mma A-fragment order: [kind][mat][a][ks][mf][lane][4] (tf32 bits)
__device__ uint32_t g_Wfrag[4 * 3 * 32768];
// Features: [kind][e][ s(0..31) | vx(32..63) | vy(64..95) | vz(96..127) ]
__device__ float g_F[(size_t)4 * EDIM * 128];

// B operands as raw fp32 bits (HW reads tf32 bit positions; implicit RZ).
#define MMA(c, A, b0, b1) \
    asm volatile("mma.sync.aligned.m16n8k8.row.col.f32.tf32.tf32.f32 " \
        "{%0,%1,%2,%3},{%4,%5,%6,%7},{%8,%9},{%0,%1,%2,%3};" \
        : "+f"((c)[0]), "+f"((c)[1]), "+f"((c)[2]), "+f"((c)[3]) \
        : "r"((A).x), "r"((A).y), "r"((A).z), "r"((A).w), "f"(b0), "f"(b1))

__device__ __forceinline__ uint32_t cvt_tf32(float p) {
    uint32_t u;
    asm("cvt.rn.tf32.f32 %0, %1;" : "=r"(u) : "f"(p));
    return u;
}

// ---------------------------------------------------------------------------
// prep (merged): blocks [0,1536) weights, [1536, 9728) features.
// ---------------------------------------------------------------------------
__global__ void prep(const float* __restrict__ x,
                     const float* __restrict__ Ws, const float* __restrict__ Wf,
                     const float* __restrict__ Wn, const float* __restrict__ Wa) {
    if (blockIdx.x < 1536) {
        int i = blockIdx.x * 256 + threadIdx.x;
        int c    = i & 3;
        int lane = (i >> 2) & 31;
        int mf   = (i >> 7) & 1;
        int ks   = (i >> 8) & 3;
        int a    = (i >> 10) & 31;
        int mk   = i >> 15;
        int mat = mk % 3, kind = mk / 3;
        const float* W = (kind == 0) ? Ws : (kind == 1) ? Wf : (kind == 2) ? Wn : Wa;
        const float norm = 0.022097086912079608f;
        const float i3   = 0.5773502691896258f;
        int g = lane >> 2, tig = lane & 3;
        int w = g + 8 * (c & 1) + 16 * mf;
        int j = 8 * ks + tig + 4 * (c >> 1);
        float val;
        if      (mat == 0) val = norm * W[(a * 32 + j) * 32 + w];
        else if (mat == 1) val = norm * i3 * W[32768 + (a * 32 + j) * 32 + w];
        else               val = norm * (W[65536 + (a * 32 + j) * 32 + w] +
                                         W[98304 + (j * 32 + a) * 32 + w]);
        g_Wfrag[i] = cvt_tf32(val);
    } else {
        int b  = (blockIdx.x - 1536) * 2 + (threadIdx.x >> 7);
        int ch = threadIdx.x & 127;
        const float* xb = x + (size_t)b * 6 * 128 + ch;
        float xv[6];
        #pragma unroll
        for (int q = 0; q < 6; q++) xv[q] = xb[q * 128];
        float r0 = xv[0]+xv[1]+xv[2], r1 = xv[3]+xv[4]+xv[5];
        float c0 = xv[0]+xv[3], c1 = xv[1]+xv[4], c2 = xv[2]+xv[5];
        float tot = r0 + r1;
        int pos = (ch < 32) ? ch : 32 + ((ch - 32) % 3) * 32 + (ch - 32) / 3;
        #pragma unroll
        for (int i = 0; i < 2; i++) {
            float ri = i ? r1 : r0;
            #pragma unroll
            for (int jj = 0; jj < 3; jj++) {
                float cj = (jj == 0) ? c0 : (jj == 1) ? c1 : c2;
                float xs = xv[i * 3 + jj];
                float vals[4] = { xs, (ri - xs) * 0.5f, (cj - xs),
                                  (tot - ri - cj + xs) * 0.5f };
                size_t e = (size_t)b * 6 + i * 3 + jj;
                #pragma unroll
                for (int t = 0; t < 4; t++)
                    g_F[((size_t)t * EDIM + e) * 128 + pos] = vals[t];
            }
        }
    }
}

// ---------------------------------------------------------------------------
// Scalar kernel: y_s = W0 . (s_a s_j). 768 CTAs x 128 thr, 4 CTA/SM.
// ---------------------------------------------------------------------------
__global__ void __launch_bounds__(128, 4) petp_sc(float* __restrict__ out) {
    extern __shared__ float FS[];   // 128 x 36
    const int tid = threadIdx.x, warp = tid >> 5, lane = tid & 31;
    const int g = lane >> 2, tig = lane & 3;
    const int tileBase = blockIdx.x * 128;
    const int e0 = tileBase + warp * 32;
    const float* fr0 = FS + (warp * 32 + g) * PADS;

    float acc[2][4][4];
    #pragma unroll
    for (int mf = 0; mf < 2; ++mf)
        #pragma unroll
        for (int nf = 0; nf < 4; ++nf)
            #pragma unroll
            for (int q = 0; q < 4; ++q) acc[mf][nf][q] = 0.f;

    for (int kind = 0; kind < 4; ++kind) {
        __syncthreads();
        {
            const float4* src = (const float4*)(g_F + ((size_t)kind * EDIM + tileBase + tid) * 128);
            float4* dst = (float4*)(FS + tid * PADS);
            #pragma unroll
            for (int q = 0; q < 8; ++q) dst[q] = src[q];   // s plane
        }
        __syncthreads();

        float bs[4][8];
        #pragma unroll
        for (int nf = 0; nf < 4; ++nf)
            #pragma unroll
            for (int jj = 0; jj < 8; ++jj)
                bs[nf][jj] = fr0[nf * NFSS + tig + 4 * jj];

        const uint4* wp0 = (const uint4*)g_Wfrag + (kind * 3 + 0) * 8192;

        #pragma unroll 1
        for (int a = 0; a < 32; ++a) {
            uint4 S0[4], S1[4];
            #pragma unroll
            for (int ks = 0; ks < 4; ++ks) {
                S0[ks] = wp0[a * 256 + ks * 64 + lane];
                S1[ks] = wp0[a * 256 + ks * 64 + 32 + lane];
            }
            float al[4];
            #pragma unroll
            for (int nf = 0; nf < 4; ++nf) al[nf] = fr0[nf * NFSS + a];
            #pragma unroll
            for (int ks = 0; ks < 4; ++ks) {
                #pragma unroll
                for (int nf = 0; nf < 4; ++nf) {
                    float b0 = al[nf] * bs[nf][2 * ks];
                    float b1 = al[nf] * bs[nf][2 * ks + 1];
                    MMA(acc[0][nf], S0[ks], b0, b1);
                    MMA(acc[1][nf], S1[ks], b0, b1);
                }
            }
        }
    }
    #pragma unroll
    for (int mf = 0; mf < 2; ++mf)
        #pragma unroll
        for (int nf = 0; nf < 4; ++nf) {
            int e  = e0 + 8 * nf + 2 * tig;
            int w1 = g + 16 * mf, w2 = w1 + 8;
            float* o = out + (size_t)e * 128;
            o[w1]       = acc[mf][nf][0];
            o[128 + w1] = acc[mf][nf][1];
            o[w2]       = acc[mf][nf][2];
            o[128 + w2] = acc[mf][nf][3];
        }
}

// ---------------------------------------------------------------------------
// Gram kernel: y_s += (W1/sqrt3) . (v_a . v_j). RMW after petp_sc.
// ---------------------------------------------------------------------------
__global__ void __launch_bounds__(128, 4) petp_gram(float* __restrict__ out) {
    extern __shared__ float FG[];   // 128 x 100 : [vx | vy | vz]
    const int tid = threadIdx.x, warp = tid >> 5, lane = tid & 31;
    const int g = lane >> 2, tig = lane & 3;
    const int tileBase = blockIdx.x * 128;
    const int e0 = tileBase + warp * 32;
    const float* fr0 = FG + (warp * 32 + g) * PADG;

    float acc[2][4][4];
    #pragma unroll
    for (int mf = 0; mf < 2; ++mf)
        #pragma unroll
        for (int nf = 0; nf < 4; ++nf)
            #pragma unroll
            for (int q = 0; q < 4; ++q) acc[mf][nf][q] = 0.f;

    for (int kind = 0; kind < 4; ++kind) {
        __syncthreads();
        {
            const float4* src = (const float4*)(g_F + ((size_t)kind * EDIM + tileBase + tid) * 128);
            float4* dst = (float4*)(FG + tid * PADG);
            #pragma unroll
            for (int q = 0; q < 24; ++q) dst[q] = src[8 + q];   // v planes
        }
        __syncthreads();

        const uint4* wp1 = (const uint4*)g_Wfrag + (kind * 3 + 1) * 8192;

        #pragma unroll 1
        for (int a = 0; a < 32; ++a) {
            uint4 G0[4], G1[4];
            #pragma unroll
            for (int ks = 0; ks < 4; ++ks) {
                G0[ks] = wp1[a * 256 + ks * 64 + lane];
                G1[ks] = wp1[a * 256 + ks * 64 + 32 + lane];
            }
            float av[4][3];
            #pragma unroll
            for (int nf = 0; nf < 4; ++nf)
                #pragma unroll
                for (int k = 0; k < 3; ++k)
                    av[nf][k] = fr0[nf * NFSG + 32 * k + a];
            #pragma unroll
            for (int ks = 0; ks < 4; ++ks) {
                #pragma unroll
                for (int nf = 0; nf < 4; ++nf) {
                    int cj = tig + 8 * ks;
                    float p0 = fmaf(av[nf][0], fr0[nf*NFSG + cj],
                               fmaf(av[nf][1], fr0[nf*NFSG + 32 + cj],
                                    av[nf][2] * fr0[nf*NFSG + 64 + cj]));
                    float p1 = fmaf(av[nf][0], fr0[nf*NFSG + 4 + cj],
                               fmaf(av[nf][1], fr0[nf*NFSG + 36 + cj],
                                    av[nf][2] * fr0[nf*NFSG + 68 + cj]));
                    MMA(acc[0][nf], G0[ks], p0, p1);
                    MMA(acc[1][nf], G1[ks], p0, p1);
                }
            }
        }
    }
    #pragma unroll
    for (int mf = 0; mf < 2; ++mf)
        #pragma unroll
        for (int nf = 0; nf < 4; ++nf) {
            int e  = e0 + 8 * nf + 2 * tig;
            int w1 = g + 16 * mf, w2 = w1 + 8;
            float* o = out + (size_t)e * 128;
            o[w1]       += acc[mf][nf][0];
            o[128 + w1] += acc[mf][nf][1];
            o[w2]       += acc[mf][nf][2];
            o[128 + w2] += acc[mf][nf][3];
        }
}

// ---------------------------------------------------------------------------
// Vector kernel: one k-component per CTA. grid (768, 3) x 128 thr.
// ---------------------------------------------------------------------------
__global__ void __launch_bounds__(128, 4) petp_v(float* __restrict__ out) {
    extern __shared__ float FV[];   // 128 x 68 : [ s | v_k ]
    const int tid = threadIdx.x, warp = tid >> 5, lane = tid & 31;
    const int g = lane >> 2, tig = lane & 3;
    const int k = blockIdx.y;
    const int tileBase = blockIdx.x * 128;
    const int e0 = tileBase + warp * 32;
    const float* fr0 = FV + (warp * 32 + g) * PADV;

    float acc[2][4][4];
    #pragma unroll
    for (int mf = 0; mf < 2; ++mf)
        #pragma unroll
        for (int nf = 0; nf < 4; ++nf)
            #pragma unroll
            for (int q = 0; q < 4; ++q) acc[mf][nf][q] = 0.f;

    for (int kind = 0; kind < 4; ++kind) {
        __syncthreads();
        {
            const float4* src = (const float4*)(g_F + ((size_t)kind * EDIM + tileBase + tid) * 128);
            float4* dst = (float4*)(FV + tid * PADV);
            #pragma unroll
            for (int q = 0; q < 8; ++q) dst[q] = src[q];               // s plane
            #pragma unroll
            for (int q = 0; q < 8; ++q) dst[8 + q] = src[8 + 8*k + q]; // v_k plane
        }
        __syncthreads();

        float bv[4][8];
        #pragma unroll
        for (int nf = 0; nf < 4; ++nf)
            #pragma unroll
            for (int jj = 0; jj < 8; ++jj)
                bv[nf][jj] = fr0[nf * NFSV + 32 + tig + 4 * jj];

        const uint4* wp2 = (const uint4*)g_Wfrag + (kind * 3 + 2) * 8192;

        #pragma unroll 1
        for (int a = 0; a < 32; ++a) {
            uint4 V0[4], V1[4];
            #pragma unroll
            for (int ks = 0; ks < 4; ++ks) {
                V0[ks] = wp2[a * 256 + ks * 64 + lane];
                V1[ks] = wp2[a * 256 + ks * 64 + 32 + lane];
            }
            float al[4];
            #pragma unroll
            for (int nf = 0; nf < 4; ++nf) al[nf] = fr0[nf * NFSV + a];

            #pragma unroll
            for (int ks = 0; ks < 4; ++ks) {
                #pragma unroll
                for (int nf = 0; nf < 4; ++nf) {
                    float b0 = al[nf] * bv[nf][2 * ks];
                    float b1 = al[nf] * bv[nf][2 * ks + 1];
                    MMA(acc[0][nf], V0[ks], b0, b1);
                    MMA(acc[1][nf], V1[ks], b0, b1);
                }
            }
        }
    }
    #pragma unroll
    for (int mf = 0; mf < 2; ++mf)
        #pragma unroll
        for (int nf = 0; nf < 4; ++nf) {
            int e  = e0 + 8 * nf + 2 * tig;
            int w1 = g + 16 * mf, w2 = w1 + 8;
            int of1 = 32 + 3 * w1 + k;
            int of2 = 32 + 3 * w2 + k;
            float* o = out + (size_t)e * 128;
            o[of1]       = acc[mf][nf][0];
            o[128 + of1] = acc[mf][nf][1];
            o[of2]       = acc[mf][nf][2];
            o[128 + of2] = acc[mf][nf][3];
        }
}

// ---------------------------------------------------------------------------
extern "C" void kernel_launch(void* const* d_in, const int* in_sizes, int n_in,
                              void* d_out, int out_size) {
    const float* x  = (const float*)d_in[0];
    const float* Ws = (const float*)d_in[1];
    const float* Wf = (const float*)d_in[2];
    const float* Wn = (const float*)d_in[3];
    const float* Wa = (const float*)d_in[4];

    const int smemS = 128 * PADS * 4;   // 18432
    const int smemG = 128 * PADG * 4;   // 51200
    const int smemV = 128 * PADV * 4;   // 34816
    cudaFuncSetAttribute(petp_sc,   cudaFuncAttributeMaxDynamicSharedMemorySize, smemS);
    cudaFuncSetAttribute(petp_gram, cudaFuncAttributeMaxDynamicSharedMemorySize, smemG);
    cudaFuncSetAttribute(petp_v,    cudaFuncAttributeMaxDynamicSharedMemorySize, smemV);

    prep<<<9728, 256>>>(x, Ws, Wf, Wn, Wa);
    petp_sc<<<768, 128, smemS>>>((float*)d_out);
    petp_gram<<<768, 128, smemG>>>((float*)d_out);
    petp_v<<<dim3(768, 3), 128, smemV>>>((float*)d_out);
}